// round 2
// baseline (speedup 1.0000x reference)
#include <cuda_runtime.h>

// Scratch: per-(row, slice) partial sums. 256 rows x 8 slices. No cudaMalloc allowed.
#define NSLICE 8
__device__ float d_partial[256 * NSLICE];

// Kernel 1: grid (NSLICE, 256). Block (s, row) reduces slice s of row `row`.
// row_elems = 50176 -> 12544 float4 -> 1568 float4 per slice, 256 threads.
__global__ __launch_bounds__(256) void row_partial_kernel(const float* __restrict__ c1,
                                                          int row_elems) {
    const int row = blockIdx.y;
    const int slice = blockIdx.x;
    const int n4 = row_elems >> 2;                // 12544
    const int per_slice = n4 / NSLICE;            // 1568
    const float4* p = reinterpret_cast<const float4*>(c1 + (size_t)row * row_elems)
                      + slice * per_slice;

    float s = 0.f;
    // 1568 / 256 = 6.125 -> 6 full strides + tail; keep generic grid-stride.
    for (int i = threadIdx.x; i < per_slice; i += 256) {
        float4 v = p[i];
        s += (v.x + v.y) + (v.z + v.w);
    }

    // warp reduce
    #pragma unroll
    for (int o = 16; o > 0; o >>= 1)
        s += __shfl_xor_sync(0xffffffffu, s, o);

    __shared__ float warp_sums[8];
    const int lane = threadIdx.x & 31;
    const int wid = threadIdx.x >> 5;
    if (lane == 0) warp_sums[wid] = s;
    __syncthreads();

    if (wid == 0) {
        float t = (lane < 8) ? warp_sums[lane] : 0.f;
        #pragma unroll
        for (int o = 4; o > 0; o >>= 1)
            t += __shfl_xor_sync(0xffffffffu, t, o);
        if (lane == 0) d_partial[row * NSLICE + slice] = t;
    }
}

// Kernel 2: out[row, :] = mean[row] * c2[row, :]. Mean computed in-block from
// the 8 partials (fixed order -> deterministic; loads are L2 broadcast hits).
__global__ __launch_bounds__(256) void scale_kernel(const float* __restrict__ c2,
                                                    float* __restrict__ out,
                                                    int row_elems) {
    const int row = blockIdx.y;

    float sum = 0.f;
    #pragma unroll
    for (int k = 0; k < NSLICE; k++)
        sum += d_partial[row * NSLICE + k];
    const float m = sum / (float)row_elems;

    const size_t base = (size_t)row * row_elems;
    const float4* src = reinterpret_cast<const float4*>(c2 + base);
    float4* dst = reinterpret_cast<float4*>(out + base);
    const int i = blockIdx.x * blockDim.x + threadIdx.x;
    float4 v = src[i];
    v.x *= m; v.y *= m; v.z *= m; v.w *= m;
    dst[i] = v;
}

extern "C" void kernel_launch(void* const* d_in, const int* in_sizes, int n_in,
                              void* d_out, int out_size) {
    const float* c1 = (const float*)d_in[0];
    const float* c2 = (const float*)d_in[1];
    float* out = (float*)d_out;

    const int B = 256;
    const int row_elems = in_sizes[0] / B;  // 50176

    dim3 rgrid(NSLICE, B);                  // 8 x 256 = 2048 blocks
    row_partial_kernel<<<rgrid, 256>>>(c1, row_elems);

    const int n4_per_row = row_elems >> 2;  // 12544
    dim3 sgrid(n4_per_row / 256, B);        // 49 x 256
    scale_kernel<<<sgrid, 256>>>(c2, out, row_elems);
}

// round 3
// speedup vs baseline: 1.0087x; 1.0087x over previous
#include <cuda_runtime.h>

// Scratch (no cudaMalloc allowed).
#define NSLICE 8
__device__ float d_partial[256 * NSLICE];
__device__ float d_row_mean[256];

// Kernel 1: grid (NSLICE, 256). Block (s, row) reduces slice s of row `row`.
// row_elems = 50176 -> 12544 float4 -> 1568 float4 per slice, 256 threads.
__global__ __launch_bounds__(256) void row_partial_kernel(const float* __restrict__ c1,
                                                          int row_elems) {
    const int row = blockIdx.y;
    const int slice = blockIdx.x;
    const int n4 = row_elems >> 2;          // 12544
    const int per_slice = n4 / NSLICE;      // 1568
    const float4* p = reinterpret_cast<const float4*>(c1 + (size_t)row * row_elems)
                      + slice * per_slice;

    // Dual accumulators for ILP; 1568 = 3*512 + 32, handle tail generically.
    float s0 = 0.f, s1 = 0.f;
    int i = threadIdx.x;
    for (; i + 256 < per_slice; i += 512) {
        float4 a = p[i];
        float4 b = p[i + 256];
        s0 += (a.x + a.y) + (a.z + a.w);
        s1 += (b.x + b.y) + (b.z + b.w);
    }
    if (i < per_slice) {
        float4 a = p[i];
        s0 += (a.x + a.y) + (a.z + a.w);
    }
    float s = s0 + s1;

    #pragma unroll
    for (int o = 16; o > 0; o >>= 1)
        s += __shfl_xor_sync(0xffffffffu, s, o);

    __shared__ float warp_sums[8];
    const int lane = threadIdx.x & 31;
    const int wid = threadIdx.x >> 5;
    if (lane == 0) warp_sums[wid] = s;
    __syncthreads();

    if (wid == 0) {
        float t = (lane < 8) ? warp_sums[lane] : 0.f;
        #pragma unroll
        for (int o = 4; o > 0; o >>= 1)
            t += __shfl_xor_sync(0xffffffffu, t, o);
        if (lane == 0) d_partial[row * NSLICE + slice] = t;
    }
}

// Kernel 1b: tiny finalize — one thread per row sums its 8 partials.
__global__ __launch_bounds__(256) void finalize_kernel(int row_elems) {
    const int row = threadIdx.x;  // 256 rows, 256 threads, 1 block
    float sum = 0.f;
    #pragma unroll
    for (int k = 0; k < NSLICE; k++)
        sum += d_partial[row * NSLICE + k];
    d_row_mean[row] = sum / (float)row_elems;
}

// Kernel 2: out[row, :] = mean[row] * c2[row, :]  (exact R1 body: single
// broadcast mean load, then pure float4 stream).
__global__ __launch_bounds__(256) void scale_kernel(const float* __restrict__ c2,
                                                    float* __restrict__ out,
                                                    int row_elems) {
    const int row = blockIdx.y;
    const float m = d_row_mean[row];
    const size_t base = (size_t)row * row_elems;
    const float4* src = reinterpret_cast<const float4*>(c2 + base);
    float4* dst = reinterpret_cast<float4*>(out + base);
    const int i = blockIdx.x * blockDim.x + threadIdx.x;
    float4 v = src[i];
    v.x *= m; v.y *= m; v.z *= m; v.w *= m;
    dst[i] = v;
}

extern "C" void kernel_launch(void* const* d_in, const int* in_sizes, int n_in,
                              void* d_out, int out_size) {
    const float* c1 = (const float*)d_in[0];
    const float* c2 = (const float*)d_in[1];
    float* out = (float*)d_out;

    const int B = 256;
    const int row_elems = in_sizes[0] / B;  // 50176

    dim3 rgrid(NSLICE, B);                  // 2048 blocks
    row_partial_kernel<<<rgrid, 256>>>(c1, row_elems);

    finalize_kernel<<<1, 256>>>(row_elems);

    const int n4_per_row = row_elems >> 2;  // 12544
    dim3 sgrid(n4_per_row / 256, B);        // 49 x 256
    scale_kernel<<<sgrid, 256>>>(c2, out, row_elems);
}

// round 4
// speedup vs baseline: 1.0195x; 1.0107x over previous
#include <cuda_runtime.h>

// Scratch (no cudaMalloc allowed). __device__ globals zero-init at load.
#define NSLICE 7
__device__ float d_partial[256 * NSLICE];
__device__ float d_row_mean[256];
__device__ unsigned int d_count[256];

// Kernel 1: grid (NSLICE, 256). Block (s, row) reduces slice s of row `row`.
// 50176 floats/row -> 12544 float4 -> 1792 float4 per slice -> exactly 7 per
// thread (256 threads), fully unrolled for MLP=7. Last block per row (atomic
// counter) finalizes the mean and resets the counter for the next graph replay.
__global__ __launch_bounds__(256) void row_partial_kernel(const float* __restrict__ c1,
                                                          int row_elems) {
    const int row = blockIdx.y;
    const int slice = blockIdx.x;
    const int n4 = row_elems >> 2;
    const int per_slice = n4 / NSLICE;
    const float4* p = reinterpret_cast<const float4*>(c1 + (size_t)row * row_elems)
                      + slice * per_slice;

    float s;
    if (per_slice == 7 * 256) {
        const int i = threadIdx.x;
        // 7 independent loads issued back-to-back (front-batched -> MLP 7).
        float4 a0 = p[i];
        float4 a1 = p[i + 256];
        float4 a2 = p[i + 512];
        float4 a3 = p[i + 768];
        float4 a4 = p[i + 1024];
        float4 a5 = p[i + 1280];
        float4 a6 = p[i + 1536];
        float t0 = (a0.x + a0.y) + (a0.z + a0.w);
        float t1 = (a1.x + a1.y) + (a1.z + a1.w);
        float t2 = (a2.x + a2.y) + (a2.z + a2.w);
        float t3 = (a3.x + a3.y) + (a3.z + a3.w);
        float t4 = (a4.x + a4.y) + (a4.z + a4.w);
        float t5 = (a5.x + a5.y) + (a5.z + a5.w);
        float t6 = (a6.x + a6.y) + (a6.z + a6.w);
        s = ((t0 + t1) + (t2 + t3)) + ((t4 + t5) + t6);
    } else {
        // Generic fallback (shape-safe).
        s = 0.f;
        for (int i = threadIdx.x; i < per_slice; i += 256) {
            float4 a = p[i];
            s += (a.x + a.y) + (a.z + a.w);
        }
    }

    #pragma unroll
    for (int o = 16; o > 0; o >>= 1)
        s += __shfl_xor_sync(0xffffffffu, s, o);

    __shared__ float warp_sums[8];
    const int lane = threadIdx.x & 31;
    const int wid = threadIdx.x >> 5;
    if (lane == 0) warp_sums[wid] = s;
    __syncthreads();

    if (threadIdx.x == 0) {
        float t = 0.f;
        #pragma unroll
        for (int w = 0; w < 8; w++) t += warp_sums[w];

        d_partial[row * NSLICE + slice] = t;
        __threadfence();
        unsigned int old = atomicAdd(&d_count[row], 1u);
        if (old == (unsigned int)(gridDim.x - 1)) {
            // Last block for this row: finalize mean (fixed order = deterministic).
            const volatile float* vp = d_partial;
            float sum = 0.f;
            #pragma unroll
            for (int k = 0; k < NSLICE; k++)
                sum += vp[row * NSLICE + k];
            d_row_mean[row] = sum / (float)row_elems;
            d_count[row] = 0;  // self-reset for next graph replay
        }
    }
}

// Kernel 2: out[row, :] = mean[row] * c2[row, :]. Single broadcast mean load,
// then pure float4 stream (known-good 6.7 TB/s body).
__global__ __launch_bounds__(256) void scale_kernel(const float* __restrict__ c2,
                                                    float* __restrict__ out,
                                                    int row_elems) {
    const int row = blockIdx.y;
    const float m = d_row_mean[row];
    const size_t base = (size_t)row * row_elems;
    const float4* src = reinterpret_cast<const float4*>(c2 + base);
    float4* dst = reinterpret_cast<float4*>(out + base);
    const int i = blockIdx.x * blockDim.x + threadIdx.x;
    float4 v = src[i];
    v.x *= m; v.y *= m; v.z *= m; v.w *= m;
    dst[i] = v;
}

extern "C" void kernel_launch(void* const* d_in, const int* in_sizes, int n_in,
                              void* d_out, int out_size) {
    const float* c1 = (const float*)d_in[0];
    const float* c2 = (const float*)d_in[1];
    float* out = (float*)d_out;

    const int B = 256;
    const int row_elems = in_sizes[0] / B;  // 50176

    dim3 rgrid(NSLICE, B);                  // 7 x 256 = 1792 blocks
    row_partial_kernel<<<rgrid, 256>>>(c1, row_elems);

    const int n4_per_row = row_elems >> 2;  // 12544
    dim3 sgrid(n4_per_row / 256, B);        // 49 x 256
    scale_kernel<<<sgrid, 256>>>(c2, out, row_elems);
}